// round 2
// baseline (speedup 1.0000x reference)
#include <cuda_runtime.h>
#include <cuda_bf16.h>
#include <cstdint>

// Reference epilogue is min(max(min(yn,0),0),1) * (1/(1-p)):
//   min(yn,0) <= 0  ->  max(.,0) == 0  ->  min(0,1) == 0  ->  * scale == 0.
// Reference output is identically zero for every input, so the optimal kernel
// is a pure zero-fill of d_out (~226.5 MB of fp32 stores, DRAM-write bound).

__global__ void zero_fill_kernel(float* __restrict__ out, long long n) {
    long long n4 = n >> 2;                       // float4 chunks
    float4* out4 = reinterpret_cast<float4*>(out);
    long long stride = (long long)gridDim.x * blockDim.x;
    const float4 z = make_float4(0.f, 0.f, 0.f, 0.f);

    for (long long i = (long long)blockIdx.x * blockDim.x + threadIdx.x;
         i < n4; i += stride) {
        out4[i] = z;
    }

    // scalar tail (n not divisible by 4)
    long long tail_start = n4 << 2;
    long long t = tail_start + (long long)blockIdx.x * blockDim.x + threadIdx.x;
    if (t < n) {
        out[t] = 0.f;
    }
}

extern "C" void kernel_launch(void* const* d_in, const int* in_sizes, int n_in,
                              void* d_out, int out_size) {
    (void)d_in; (void)in_sizes; (void)n_in;

    long long n = (long long)out_size;   // fp32 element count
    const int threads = 256;
    // Enough CTAs to fill the chip with several waves of independent stores:
    // ~8 CTAs per SM on a ~148-SM part. Grid-stride handles any remainder.
    int blocks = 148 * 8;
    long long n4 = n >> 2;
    if (n4 < (long long)blocks * threads) {
        blocks = (int)((n4 + threads - 1) / threads);
        if (blocks < 1) blocks = 1;
    }
    zero_fill_kernel<<<blocks, threads>>>((float*)d_out, n);
}

// round 5
// speedup vs baseline: 1.1189x; 1.1189x over previous
#include <cuda_runtime.h>
#include <cuda_bf16.h>
#include <cstdint>

// Reference epilogue is min(max(min(yn,0),0),1) * (1/(1-p)):
//   min(yn,0) <= 0  ->  max(.,0) == 0  ->  everything after preserves 0.
// Reference output is identically zero, so the kernel is a pure zero-fill of
// d_out (~226.5 MB fp32 stores). DRAM-write bound; goal: saturate store path.
//
// R2 passing: 37.5us @ DRAM 55% with 1 STG.128/iter. This version issues 4
// independent coalesced STG.128 per thread per iteration (4x store MLP) and a
// 148*16 grid to keep the L1tex->L2 store queues full.
// (R3/R4 submissions of this kernel hit broker infra failures; never ran.)

__global__ void zero_fill_kernel(float* __restrict__ out, long long n) {
    long long n4 = n >> 2;                       // float4 chunks
    float4* __restrict__ out4 = reinterpret_cast<float4*>(out);
    const float4 z = make_float4(0.f, 0.f, 0.f, 0.f);

    const long long bsz = blockDim.x;
    // Each block-iteration covers blockDim*4 float4 chunks, fully coalesced:
    // store j covers [base + j*bsz, base + (j+1)*bsz), lane offset = tid.
    const long long iter_span = (long long)gridDim.x * bsz * 4;
    long long base = (long long)blockIdx.x * bsz * 4 + threadIdx.x;

    // Fast path: full tiles, 4 independent unguarded STG.128 per iteration.
    for (; base + 3 * bsz < n4; base += iter_span) {
        out4[base]           = z;
        out4[base + bsz]     = z;
        out4[base + 2 * bsz] = z;
        out4[base + 3 * bsz] = z;
    }
    // One guarded epilogue tile per thread (loop exits with base in the last,
    // possibly-partial tile for this thread's stride sequence).
    #pragma unroll
    for (int j = 0; j < 4; j++) {
        long long idx = base + (long long)j * bsz;
        if (idx < n4) out4[idx] = z;
    }
    // Scalar tail (n not divisible by 4).
    long long tail_start = n4 << 2;
    long long t = tail_start + (long long)blockIdx.x * bsz + threadIdx.x;
    if (t < n) out[t] = 0.f;
}

extern "C" void kernel_launch(void* const* d_in, const int* in_sizes, int n_in,
                              void* d_out, int out_size) {
    (void)d_in; (void)in_sizes; (void)n_in;

    long long n = (long long)out_size;   // fp32 element count
    const int threads = 256;
    int blocks = 148 * 16;               // deep store concurrency per SM
    long long n4 = n >> 2;
    long long needed = (n4 + threads * 4 - 1) / (threads * 4);
    if (needed < blocks) blocks = (int)(needed > 0 ? needed : 1);
    zero_fill_kernel<<<blocks, threads>>>((float*)d_out, n);
}